// round 6
// baseline (speedup 1.0000x reference)
#include <cuda_runtime.h>

// Elementwise CGP model — R5 winner + evict-first loads (full streaming policy).
//   n7 = __sinf(x0*x1 + c0) * (x2*x3) + __sinf(x2)
//   n8 = __cosf(n7)*c1 + x0
//
// Block owns 1024 consecutive rows; thread t handles rows base + 256*k + t,
// k = 0..3:
//   - 4 front-batched LDG.128 via __ldcs (X is a zero-reuse 134MB stream:
//     evict-first keeps it from displacing resident output lines in L2)
//   - 4 STG.64 via __stcs (write-once output)

__device__ __forceinline__ float2 cgp_row(float4 x, float c0, float c1) {
    float n4 = __fmaf_rn(x.x, x.y, c0);
    float n5 = __sinf(n4);
    float n6 = x.z * x.w;
    float n7 = __fmaf_rn(n5, n6, __sinf(x.z));
    float n8 = __fmaf_rn(__cosf(n7), c1, x.x);
    return make_float2(n7, n8);
}

__global__ void __launch_bounds__(256, 8)
cgp_kernel(const float4* __restrict__ X,
           const float* __restrict__ ephs,
           float2* __restrict__ out) {
    const int base = blockIdx.x * 1024 + threadIdx.x;

    const float c0 = __ldg(&ephs[0]);
    const float c1 = __ldg(&ephs[1]);

    // Front-batched coalesced streaming loads, MLP=4.
    float4 a = __ldcs(&X[base + 0]);
    float4 b = __ldcs(&X[base + 256]);
    float4 c = __ldcs(&X[base + 512]);
    float4 d = __ldcs(&X[base + 768]);

    float2 ra = cgp_row(a, c0, c1);
    float2 rb = cgp_row(b, c0, c1);
    float2 rc = cgp_row(c, c0, c1);
    float2 rd = cgp_row(d, c0, c1);

    __stcs(&out[base + 0],   ra);
    __stcs(&out[base + 256], rb);
    __stcs(&out[base + 512], rc);
    __stcs(&out[base + 768], rd);
}

extern "C" void kernel_launch(void* const* d_in, const int* in_sizes, int n_in,
                              void* d_out, int out_size) {
    const float4* X   = (const float4*)d_in[0];   // (B, 4) float32, one float4/row
    const float*  eph = (const float*)d_in[1];    // (2,)   float32
    float2*       out = (float2*)d_out;           // (B, 2) float32, one float2/row

    int B = in_sizes[0] / 4;       // rows = 8388608
    int blocks = B / 1024;         // 1024 rows per block (B divisible)

    cgp_kernel<<<blocks, 256>>>(X, eph, out);
}